// round 5
// baseline (speedup 1.0000x reference)
#include <cuda_runtime.h>

#define N_BINS 85
#define NBLOCKS 1184            // 8 CTAs/SM * 148 SMs (empirical best shape)
#define GROUPS_PER_BLOCK 3
#define ACTIVE_THREADS (GROUPS_PER_BLOCK * N_BINS)   // 255
#define BLOCK_THREADS 256
#define ROWS_PER_GROUP 2        // super-rows per group per grab
#define CHUNK_SUPER (GROUPS_PER_BLOCK * ROWS_PER_GROUP)   // 6 super-rows per chunk

// Globals (zero at load; reset by the last block each call so graph replays
// are deterministic). No dynamic allocation allowed.
__device__ float g_acc[N_BINS];
__device__ unsigned int g_count;
__device__ unsigned int g_work;

// ---------------------------------------------------------------------------
// Fused, dynamically scheduled column reduction.
// Work unit ("chunk") = 6 super-rows (1 super-row = 4 rows = 85 float4s).
// CTAs pull chunk ids from g_work via atomicAdd: fast SMs do more chunks,
// eliminating the static-partition straggler tail (L2-die speed variance).
// Group g = t/85 handles super-rows chunk*6 + g*2 + {0,1}; position p = t%85.
// Epilogue: block partials -> global float atomics -> last block finishes.
// ---------------------------------------------------------------------------
__global__ void __launch_bounds__(BLOCK_THREADS, 8)
emd_fused(const float4* __restrict__ in4, const float4* __restrict__ tg4,
          const float* __restrict__ in, const float* __restrict__ tg,
          int nchunk, int tail_start, int total_elems, float* __restrict__ out)
{
    __shared__ float sd[N_BINS];
    __shared__ unsigned int s_next;
    __shared__ int islast;
    int t = threadIdx.x;
    if (t < N_BINS) sd[t] = 0.0f;

    int g = t / N_BINS;          // 0..2 (t<255), 3 for t=255 (inactive)
    int p = t % N_BINS;

    float a0 = 0.f, a1 = 0.f, a2 = 0.f, a3 = 0.f;

    if (t == 0) s_next = atomicAdd(&g_work, 1u);
    __syncthreads();
    unsigned int cur = s_next;

    while (cur < (unsigned)nchunk) {
        __syncthreads();                       // everyone has read s_next
        if (t == 0) s_next = atomicAdd(&g_work, 1u);   // prefetch next chunk id

        if (t < ACTIVE_THREADS) {
            int i0 = ((int)cur * CHUNK_SUPER + g * ROWS_PER_GROUP) * N_BINS + p;
            float4 xa = __ldcs(&in4[i0]);
            float4 xb = __ldcs(&tg4[i0]);
            float4 ya = __ldcs(&in4[i0 + N_BINS]);
            float4 yb = __ldcs(&tg4[i0 + N_BINS]);
            a0 += (xa.x - xb.x) + (ya.x - yb.x);
            a1 += (xa.y - xb.y) + (ya.y - yb.y);
            a2 += (xa.z - xb.z) + (ya.z - yb.z);
            a3 += (xa.w - xb.w) + (ya.w - yb.w);
        }
        __syncthreads();                       // s_next write visible
        cur = s_next;
    }

    // Fold 4 register lanes into fixed columns (4p+k) mod 85.
    if (t < ACTIVE_THREADS) {
        atomicAdd(&sd[(4 * p) % N_BINS],     a0);
        atomicAdd(&sd[(4 * p + 1) % N_BINS], a1);
        atomicAdd(&sd[(4 * p + 2) % N_BINS], a2);
        atomicAdd(&sd[(4 * p + 3) % N_BINS], a3);
    }
    // Remainder (super-rows not covered by chunks + row tail): block 0, scalar.
    if (blockIdx.x == 0) {
        for (int i = tail_start + t; i < total_elems; i += BLOCK_THREADS) {
            atomicAdd(&sd[i % N_BINS], in[i] - tg[i]);
        }
    }
    __syncthreads();

    // Publish block partials via L2 float atomics (85 distinct addresses).
    if (t < N_BINS) atomicAdd(&g_acc[t], sd[t]);
    __threadfence();          // release: my atomics visible before my ticket
    __syncthreads();
    if (t == 0) {
        unsigned int ticket = atomicAdd(&g_count, 1u);
        islast = (ticket == NBLOCKS - 1u);
    }
    __syncthreads();

    if (islast) {
        __shared__ float d[N_BINS];
        __threadfence();      // acquire
        if (t < N_BINS) {
            float v = *((volatile float*)&g_acc[t]);
            g_acc[t] = 0.0f;                   // reset for next graph replay
            d[t] = fabsf(v);
        }
        __syncthreads();
        if (t == 0) {
            float cum = 0.f, loss = 0.f;
            #pragma unroll
            for (int j = 0; j < N_BINS; j++) {
                cum += d[j];
                loss += cum / (float)(j + 1);
            }
            out[0] = loss * 0.1f;
            g_count = 0u;
            g_work  = 0u;                      // reset work queue
        }
    }
}

extern "C" void kernel_launch(void* const* d_in, const int* in_sizes, int n_in,
                              void* d_out, int out_size)
{
    const float* in = (const float*)d_in[0];
    const float* tg = (const float*)d_in[1];
    int total = in_sizes[0];                 // 500000 * 85
    int B = total / N_BINS;
    int nsuper = B / 4;                      // 125000
    int nchunk = nsuper / CHUNK_SUPER;       // 20833
    int tail_start = nchunk * CHUNK_SUPER * (4 * N_BINS);  // element index

    emd_fused<<<NBLOCKS, BLOCK_THREADS>>>((const float4*)in, (const float4*)tg,
                                          in, tg, nchunk, tail_start, total,
                                          (float*)d_out);
}